// round 1
// baseline (speedup 1.0000x reference)
#include <cuda_runtime.h>

#define NN   8192
#define DIN  512
#define DOUT 256

// Scratch (allocation-free rule: __device__ globals)
__device__ float g_hW[NN * DOUT];   // 8 MB
__device__ float g_f1[NN];
__device__ float g_f2[NN];

// ---------------------------------------------------------------------------
// Kernel A: g_hW = h @ W     (8192x512 @ 512x256)
// 64x64 tile per block, 256 threads, 4x4 micro-tile, fp32.
// ---------------------------------------------------------------------------
__global__ __launch_bounds__(256) void k_gemm_hw(
    const float* __restrict__ h, const float* __restrict__ W)
{
    __shared__ float As[32][64];   // [k][m]
    __shared__ float Bs[32][64];   // [k][n]

    const int tid = threadIdx.x;
    const int c0  = blockIdx.x * 64;
    const int i0  = blockIdx.y * 64;
    const int tx  = tid & 15;      // col group (4 cols)
    const int ty  = tid >> 4;      // row group (4 rows)

    const int li  = tid >> 2;            // 0..63  A-load row
    const int lk  = (tid & 3) * 8;       // A-load k base

    const int bk  = tid >> 4;            // 0..15  B-load k
    const int bc  = (tid & 15) * 4;      // B-load col

    float acc[4][4] = {};

    for (int k0 = 0; k0 < DIN; k0 += 32) {
        float4 a0 = *(const float4*)&h[(i0 + li) * DIN + k0 + lk];
        float4 a1 = *(const float4*)&h[(i0 + li) * DIN + k0 + lk + 4];
        float4 b0 = *(const float4*)&W[(k0 + bk) * DOUT + c0 + bc];
        float4 b1 = *(const float4*)&W[(k0 + bk + 16) * DOUT + c0 + bc];

        __syncthreads();
        As[lk + 0][li] = a0.x; As[lk + 1][li] = a0.y;
        As[lk + 2][li] = a0.z; As[lk + 3][li] = a0.w;
        As[lk + 4][li] = a1.x; As[lk + 5][li] = a1.y;
        As[lk + 6][li] = a1.z; As[lk + 7][li] = a1.w;
        *(float4*)&Bs[bk][bc]      = b0;
        *(float4*)&Bs[bk + 16][bc] = b1;
        __syncthreads();

        #pragma unroll
        for (int k = 0; k < 32; k++) {
            float4 af = *(const float4*)&As[k][ty * 4];
            float4 bf = *(const float4*)&Bs[k][tx * 4];
            float ar[4] = {af.x, af.y, af.z, af.w};
            float br[4] = {bf.x, bf.y, bf.z, bf.w};
            #pragma unroll
            for (int r = 0; r < 4; r++)
                #pragma unroll
                for (int c = 0; c < 4; c++)
                    acc[r][c] = fmaf(ar[r], br[c], acc[r][c]);
        }
    }

    #pragma unroll
    for (int r = 0; r < 4; r++) {
        float4 v = make_float4(acc[r][0], acc[r][1], acc[r][2], acc[r][3]);
        *(float4*)&g_hW[(i0 + ty * 4 + r) * DOUT + c0 + tx * 4] = v;
    }
}

// ---------------------------------------------------------------------------
// Kernel B: f1 = hW @ a[:256],  f2 = hW @ a[256:]
// One warp per row, 8 rows per block.
// ---------------------------------------------------------------------------
__global__ void k_f1f2(const float* __restrict__ a)
{
    const int row  = blockIdx.x * 8 + threadIdx.y;
    const int lane = threadIdx.x;
    const float* hw = &g_hW[row * DOUT];

    float s1 = 0.f, s2 = 0.f;
    #pragma unroll
    for (int c = 0; c < DOUT; c += 32) {
        float v = hw[c + lane];
        s1 = fmaf(v, a[c + lane], s1);
        s2 = fmaf(v, a[DOUT + c + lane], s2);
    }
    #pragma unroll
    for (int off = 16; off; off >>= 1) {
        s1 += __shfl_xor_sync(0xffffffffu, s1, off);
        s2 += __shfl_xor_sync(0xffffffffu, s2, off);
    }
    if (lane == 0) { g_f1[row] = s1; g_f2[row] = s2; }
}

// ---------------------------------------------------------------------------
// Kernel C: fused masked softmax aggregation + ELU.
// out[i,:] = elu( (sum_j adj_ij * w_ij * hW[j,:]) / (sum_j adj_ij * w_ij) )
//   w_ij = expf(leaky(f1_i + f2_j))   -- fp32 range-safe, no max pass needed.
// Block = 64 rows x 256 cols, 256 threads, 8x8 micro-tile, fma.rn.f32x2.
// w stored in SMEM pre-duplicated as (w,w) 64-bit pairs -> no packing in loop.
// adj/hW/f2 for tile t+1 prefetched into registers during FMA loop of tile t.
// ---------------------------------------------------------------------------
__global__ __launch_bounds__(256, 1) void k_gat(
    const int* __restrict__ adj, float* __restrict__ out)
{
    __shared__ unsigned long long w2s[32][64];  // 16 KB  [k][i], value=(w,w)
    __shared__ float bs[32][256];               // 32 KB  [k][c] hW tile

    const int tid = threadIdx.x;
    const int i0  = blockIdx.x * 64;
    const int tx  = tid & 31;   // col group: cols {tx*4..+3, 128+tx*4..+3}
    const int ty  = tid >> 5;   // row group: rows ty*8..+7

    // w-phase mapping: this thread computes w for row iw, k = kb..kb+7
    const int iw = tid >> 2;          // 0..63
    const int kb = (tid & 3) << 3;    // 0,8,16,24
    const float f1v = g_f1[i0 + iw];

    // hW tile load mapping: 8 x float4, rows bkr+4s, col 4*bc4
    const int bkr = tid >> 6;         // 0..3
    const int bc4 = tid & 63;         // 0..63

    unsigned long long acc[8][4];
    #pragma unroll
    for (int r = 0; r < 8; r++)
        #pragma unroll
        for (int c = 0; c < 4; c++) acc[r][c] = 0ull;

    float zacc = 0.f;   // used by tid < 64 (row-sum of w)

    // Prefetch registers
    int4   adjA, adjB;
    float4 hwp[8];
    float4 f2a, f2b;

    auto prefetch = [&](int j0) {
        const int* ap = &adj[(i0 + iw) * NN + j0 + kb];
        adjA = *(const int4*)ap;
        adjB = *(const int4*)(ap + 4);
        #pragma unroll
        for (int s = 0; s < 8; s++)
            hwp[s] = *(const float4*)&g_hW[(j0 + bkr + 4 * s) * DOUT + bc4 * 4];
        f2a = *(const float4*)&g_f2[j0 + kb];
        f2b = *(const float4*)&g_f2[j0 + kb + 4];
    };

    prefetch(0);

    for (int jt = 0; jt < NN / 32; ++jt) {
        __syncthreads();   // previous tile's SMEM consumers done

        // ---- write phase: w tile + hW tile into SMEM ----
        {
            const float f2r[8] = {f2a.x, f2a.y, f2a.z, f2a.w,
                                  f2b.x, f2b.y, f2b.z, f2b.w};
            const int   avv[8] = {adjA.x, adjA.y, adjA.z, adjA.w,
                                  adjB.x, adjB.y, adjB.z, adjB.w};
            #pragma unroll
            for (int s = 0; s < 8; s++) {
                float e = f1v + f2r[s];
                e = (e > 0.f) ? e : 0.2f * e;
                float w = (avv[s] > 0) ? __expf(e) : 0.f;
                unsigned wu = __float_as_uint(w);
                unsigned long long p;
                asm("mov.b64 %0, {%1, %1};" : "=l"(p) : "r"(wu));
                w2s[kb + s][iw] = p;
            }
            #pragma unroll
            for (int s = 0; s < 8; s++)
                *(float4*)&bs[bkr + 4 * s][bc4 * 4] = hwp[s];
        }
        __syncthreads();

        if (jt + 1 < NN / 32) prefetch((jt + 1) * 32);

        // ---- FMA phase ----
        #pragma unroll 4
        for (int k = 0; k < 32; k++) {
            ulonglong2 b01 = *(const ulonglong2*)&bs[k][tx * 4];
            ulonglong2 b23 = *(const ulonglong2*)&bs[k][128 + tx * 4];
            unsigned long long bp[4] = {b01.x, b01.y, b23.x, b23.y};

            const unsigned long long* wrow = &w2s[k][ty * 8];
            ulonglong2 a01 = *(const ulonglong2*)(wrow + 0);
            ulonglong2 a23 = *(const ulonglong2*)(wrow + 2);
            ulonglong2 a45 = *(const ulonglong2*)(wrow + 4);
            ulonglong2 a67 = *(const ulonglong2*)(wrow + 6);
            unsigned long long apk[8] = {a01.x, a01.y, a23.x, a23.y,
                                         a45.x, a45.y, a67.x, a67.y};
            #pragma unroll
            for (int r = 0; r < 8; r++)
                #pragma unroll
                for (int c = 0; c < 4; c++)
                    asm("fma.rn.f32x2 %0, %1, %2, %0;"
                        : "+l"(acc[r][c]) : "l"(apk[r]), "l"(bp[c]));
        }

        // ---- Z drain: row-sums of this tile's w (low half of (w,w)) ----
        if (tid < 64) {
            float z = zacc;
            #pragma unroll 8
            for (int k = 0; k < 32; k++)
                z += *((const float*)&w2s[k][tid]);   // low 32 bits = w
            zacc = z;
        }
    }

    // ---- epilogue: divide by Z, ELU, store ----
    __syncthreads();                  // all FMA reads of bs done
    float* zsp = (float*)bs;          // reuse bs for Z broadcast
    if (tid < 64) zsp[tid] = zacc;
    __syncthreads();

    #pragma unroll
    for (int r = 0; r < 8; r++) {
        const float zi = 1.0f / zsp[ty * 8 + r];
        float o[8];
        #pragma unroll
        for (int c = 0; c < 4; c++) {
            float lo = __uint_as_float((unsigned)(acc[r][c] & 0xffffffffull));
            float hi = __uint_as_float((unsigned)(acc[r][c] >> 32));
            float v0 = lo * zi, v1 = hi * zi;
            o[2 * c + 0] = (v0 > 0.f) ? v0 : expm1f(v0);
            o[2 * c + 1] = (v1 > 0.f) ? v1 : expm1f(v1);
        }
        float* orow = &out[(i0 + ty * 8 + r) * DOUT];
        *(float4*)(orow + tx * 4)       = make_float4(o[0], o[1], o[2], o[3]);
        *(float4*)(orow + 128 + tx * 4) = make_float4(o[4], o[5], o[6], o[7]);
    }
}

// ---------------------------------------------------------------------------
extern "C" void kernel_launch(void* const* d_in, const int* in_sizes, int n_in,
                              void* d_out, int out_size)
{
    const float* h   = (const float*)d_in[0];   // [8192, 512]
    const int*   adj = (const int*)  d_in[1];   // [8192, 8192]
    const float* W   = (const float*)d_in[2];   // [512, 256]
    const float* a   = (const float*)d_in[3];   // [512, 1]
    float* out = (float*)d_out;                 // [8192, 256]

    k_gemm_hw<<<dim3(DOUT / 64, NN / 64), 256>>>(h, W);
    k_f1f2<<<NN / 8, dim3(32, 8)>>>(a);
    k_gat<<<NN / 64, 256>>>(adj, out);
}

// round 3
// speedup vs baseline: 2.1151x; 2.1151x over previous
#include <cuda_runtime.h>
#include <cuda_bf16.h>
#include <cstdint>

#define NN   8192
#define DIN  512
#define DOUT 256
#define KSLICES 2
#define KSL  (NN / KSLICES)     // 4096 k per slice
#define KT   64                 // k per chunk
#define NCHUNK (KSL / KT)       // 64

// ---------------- scratch (__device__ globals: allocation-free rule) --------
__device__ float          g_hW   [(size_t)NN * DOUT];     // fp32 hW (for f1f2)
__device__ float          g_f1   [NN];
__device__ float          g_f2   [NN];
__device__ unsigned short g_hWT_hi[(size_t)DOUT * NN];    // hW^T bf16 hi [col][row]
__device__ unsigned short g_hWT_lo[(size_t)DOUT * NN];    // hW^T bf16 lo
__device__ float          g_np   [(size_t)KSLICES * NN * DOUT]; // partial numerators
__device__ float          g_zp   [KSLICES * NN];                // partial Z

// ---------------- helpers ---------------------------------------------------
__device__ __forceinline__ uint32_t smem_u32(const void* p) {
    uint32_t a;
    asm("{ .reg .u64 t; cvta.to.shared.u64 t, %1; cvt.u32.u64 %0, t; }"
        : "=r"(a) : "l"(p));
    return a;
}
__device__ __forceinline__ uint32_t sw128(uint32_t off) {
    return off ^ ((off >> 3) & 0x70);
}
__device__ __forceinline__ unsigned pack_bf16x2(float lo, float hi) {
    unsigned r;
    asm("cvt.rn.bf16x2.f32 %0, %1, %2;" : "=r"(r) : "f"(hi), "f"(lo));
    return r;   // low 16 = bf16(lo), high 16 = bf16(hi)
}
__device__ __forceinline__ float bf_lo(unsigned p) { return __uint_as_float(p << 16); }
__device__ __forceinline__ float bf_hi(unsigned p) { return __uint_as_float(p & 0xffff0000u); }

__device__ __forceinline__ void cp16(uint32_t smem, const void* g) {
    asm volatile("cp.async.cg.shared.global [%0], [%1], 16;"
                 :: "r"(smem), "l"(g));
}
__device__ __forceinline__ void cp_commit() {
    asm volatile("cp.async.commit_group;");
}
__device__ __forceinline__ void cp_wait0() {
    asm volatile("cp.async.wait_group 0;" ::: "memory");
}
__device__ __forceinline__ void ldsm4(uint32_t* r, uint32_t addr) {
    asm volatile("ldmatrix.sync.aligned.m8n8.x4.shared.b16 {%0,%1,%2,%3}, [%4];"
                 : "=r"(r[0]), "=r"(r[1]), "=r"(r[2]), "=r"(r[3]) : "r"(addr));
}
__device__ __forceinline__ void mma16816(float* c, const uint32_t* a,
                                         uint32_t b0, uint32_t b1) {
    asm volatile(
        "mma.sync.aligned.m16n8k16.row.col.f32.bf16.bf16.f32 "
        "{%0,%1,%2,%3},{%4,%5,%6,%7},{%8,%9},{%0,%1,%2,%3};"
        : "+f"(c[0]), "+f"(c[1]), "+f"(c[2]), "+f"(c[3])
        : "r"(a[0]), "r"(a[1]), "r"(a[2]), "r"(a[3]), "r"(b0), "r"(b1));
}

// ---------------------------------------------------------------------------
// Kernel A: g_hW = h @ W  (fp32)  +  epilogue: g_hWT hi/lo bf16 (transposed)
// ---------------------------------------------------------------------------
__global__ __launch_bounds__(256) void k_gemm_hw(
    const float* __restrict__ h, const float* __restrict__ W)
{
    __shared__ float As[32][64];
    __shared__ float Bs[32][64];

    const int tid = threadIdx.x;
    const int c0  = blockIdx.x * 64;
    const int i0  = blockIdx.y * 64;
    const int tx  = tid & 15;
    const int ty  = tid >> 4;
    const int li  = tid >> 2;
    const int lk  = (tid & 3) * 8;
    const int bk  = tid >> 4;
    const int bc  = (tid & 15) * 4;

    float acc[4][4] = {};

    for (int k0 = 0; k0 < DIN; k0 += 32) {
        float4 a0 = *(const float4*)&h[(i0 + li) * DIN + k0 + lk];
        float4 a1 = *(const float4*)&h[(i0 + li) * DIN + k0 + lk + 4];
        float4 b0 = *(const float4*)&W[(k0 + bk) * DOUT + c0 + bc];
        float4 b1 = *(const float4*)&W[(k0 + bk + 16) * DOUT + c0 + bc];

        __syncthreads();
        As[lk + 0][li] = a0.x; As[lk + 1][li] = a0.y;
        As[lk + 2][li] = a0.z; As[lk + 3][li] = a0.w;
        As[lk + 4][li] = a1.x; As[lk + 5][li] = a1.y;
        As[lk + 6][li] = a1.z; As[lk + 7][li] = a1.w;
        *(float4*)&Bs[bk][bc]      = b0;
        *(float4*)&Bs[bk + 16][bc] = b1;
        __syncthreads();

        #pragma unroll
        for (int k = 0; k < 32; k++) {
            float4 af = *(const float4*)&As[k][ty * 4];
            float4 bf = *(const float4*)&Bs[k][tx * 4];
            float ar[4] = {af.x, af.y, af.z, af.w};
            float br[4] = {bf.x, bf.y, bf.z, bf.w};
            #pragma unroll
            for (int r = 0; r < 4; r++)
                #pragma unroll
                for (int c = 0; c < 4; c++)
                    acc[r][c] = fmaf(ar[r], br[c], acc[r][c]);
        }
    }

    #pragma unroll
    for (int r = 0; r < 4; r++) {
        float4 v = make_float4(acc[r][0], acc[r][1], acc[r][2], acc[r][3]);
        *(float4*)&g_hW[(size_t)(i0 + ty * 4 + r) * DOUT + c0 + tx * 4] = v;
    }
    // transposed bf16 hi/lo
    #pragma unroll
    for (int cc = 0; cc < 4; cc++) {
        const int c = c0 + tx * 4 + cc;
        unsigned p01 = pack_bf16x2(acc[0][cc], acc[1][cc]);
        unsigned p23 = pack_bf16x2(acc[2][cc], acc[3][cc]);
        float l0 = acc[0][cc] - bf_lo(p01);
        float l1 = acc[1][cc] - bf_hi(p01);
        float l2 = acc[2][cc] - bf_lo(p23);
        float l3 = acc[3][cc] - bf_hi(p23);
        unsigned q01 = pack_bf16x2(l0, l1);
        unsigned q23 = pack_bf16x2(l2, l3);
        size_t base = (size_t)c * NN + i0 + ty * 4;
        *(uint2*)(g_hWT_hi + base) = make_uint2(p01, p23);
        *(uint2*)(g_hWT_lo + base) = make_uint2(q01, q23);
    }
}

// ---------------------------------------------------------------------------
// Kernel B: f1 = hW @ a[:256],  f2 = hW @ a[256:]
// ---------------------------------------------------------------------------
__global__ void k_f1f2(const float* __restrict__ a)
{
    const int row  = blockIdx.x * 8 + threadIdx.y;
    const int lane = threadIdx.x;
    const float* hw = &g_hW[(size_t)row * DOUT];

    float s1 = 0.f, s2 = 0.f;
    #pragma unroll
    for (int c = 0; c < DOUT; c += 32) {
        float v = hw[c + lane];
        s1 = fmaf(v, a[c + lane], s1);
        s2 = fmaf(v, a[DOUT + c + lane], s2);
    }
    #pragma unroll
    for (int off = 16; off; off >>= 1) {
        s1 += __shfl_xor_sync(0xffffffffu, s1, off);
        s2 += __shfl_xor_sync(0xffffffffu, s2, off);
    }
    if (lane == 0) { g_f1[row] = s1; g_f2[row] = s2; }
}

// ---------------------------------------------------------------------------
// Kernel C: warp-MMA (mma.sync bf16) fused masked-softmax aggregation.
// Grid (64, KSLICES), 512 threads (16 warps, 4m x 4n).
// CTA tile: M=128 rows, N=256 cols, K streamed in Kt=64 chunks.
// A = w (computed in-kernel, bf16 hi/lo), B = hW^T (bf16 hi/lo via cp.async).
// 3 products: Ah*Bh + Ah*Bl + Al*Bh, fp32 register accumulators.
// ---------------------------------------------------------------------------
// SMEM: [0..2KB) zbuf; stages at 2KB: per stage A_hi 16K | A_lo 16K | B_hi 32K | B_lo 32K
#define ZOFF        0
#define TILE0       2048
#define STAGE_BYTES 98304
#define SMEM_TOTAL  (TILE0 + 2 * STAGE_BYTES)

__global__ __launch_bounds__(512, 1) void k_gat_mma(const int* __restrict__ adj)
{
    extern __shared__ __align__(1024) char smem[];
    const uint32_t sb = smem_u32(smem);

    const int tid  = threadIdx.x;
    const int lane = tid & 31;
    const int wid  = tid >> 5;
    const int wm   = wid & 3;      // warp row  (32 rows)
    const int wn   = wid >> 2;     // warp col  (64 cols)
    const int i0   = blockIdx.x * 128;
    const int ks   = blockIdx.y;
    const int k0s  = ks * KSL;

    int AHI[2], ALO[2], BHI[2], BLO[2];
    #pragma unroll
    for (int s = 0; s < 2; s++) {
        AHI[s] = TILE0 + s * STAGE_BYTES;
        ALO[s] = AHI[s] + 16384;
        BHI[s] = AHI[s] + 32768;
        BLO[s] = AHI[s] + 65536;
    }

    // ---- w-gen mapping: row iw, 16 k's starting at kb ----
    const int iw = tid >> 2;
    const int kb = (tid & 3) * 16;
    const float f1v = g_f1[i0 + iw];
    float zacc = 0.f;

    // ---- B cp.async mapping: n-row rB, 4 chunks of 16B ----
    const int rB   = tid & 255;
    const int half = tid >> 8;

    float acc[2][8][4];
    #pragma unroll
    for (int mt = 0; mt < 2; mt++)
        #pragma unroll
        for (int nt = 0; nt < 8; nt++)
            #pragma unroll
            for (int q = 0; q < 4; q++) acc[mt][nt][q] = 0.f;

    auto load_B = [&](int jt, int s) {
        const size_t gk = (size_t)rB * NN + k0s + jt * KT;
        #pragma unroll
        for (int c = 0; c < 4; c++) {
            const int cc = half * 4 + c;
            const uint32_t off = sw128((uint32_t)(rB * 128 + cc * 16));
            cp16(sb + BHI[s] + off, g_hWT_hi + gk + cc * 8);
            cp16(sb + BLO[s] + off, g_hWT_lo + gk + cc * 8);
        }
    };

    auto gen_A = [&](int jt, int s) {
        const size_t kg = (size_t)k0s + jt * KT + kb;
        const int4*   ap = (const int4*)  (adj  + (size_t)(i0 + iw) * NN + kg);
        const float4* fp = (const float4*)(g_f2 + kg);
        int4   A0 = ap[0], A1 = ap[1], A2 = ap[2], A3 = ap[3];
        float4 F0 = fp[0], F1 = fp[1], F2 = fp[2], F3 = fp[3];
        const int   av[16] = {A0.x,A0.y,A0.z,A0.w, A1.x,A1.y,A1.z,A1.w,
                              A2.x,A2.y,A2.z,A2.w, A3.x,A3.y,A3.z,A3.w};
        const float fv[16] = {F0.x,F0.y,F0.z,F0.w, F1.x,F1.y,F1.z,F1.w,
                              F2.x,F2.y,F2.z,F2.w, F3.x,F3.y,F3.z,F3.w};
        float w[16];
        #pragma unroll
        for (int q = 0; q < 16; q++) {
            float e = f1v + fv[q];
            e = (e > 0.f) ? e : 0.2f * e;
            float we = __expf(e);
            w[q] = (av[q] > 0) ? we : 0.f;
            zacc += w[q];
        }
        uint4 H0, H1, L0, L1;
        H0.x = pack_bf16x2(w[0],  w[1]);  H0.y = pack_bf16x2(w[2],  w[3]);
        H0.z = pack_bf16x2(w[4],  w[5]);  H0.w = pack_bf16x2(w[6],  w[7]);
        H1.x = pack_bf16x2(w[8],  w[9]);  H1.y = pack_bf16x2(w[10], w[11]);
        H1.z = pack_bf16x2(w[12], w[13]); H1.w = pack_bf16x2(w[14], w[15]);
        L0.x = pack_bf16x2(w[0]  - bf_lo(H0.x), w[1]  - bf_hi(H0.x));
        L0.y = pack_bf16x2(w[2]  - bf_lo(H0.y), w[3]  - bf_hi(H0.y));
        L0.z = pack_bf16x2(w[4]  - bf_lo(H0.z), w[5]  - bf_hi(H0.z));
        L0.w = pack_bf16x2(w[6]  - bf_lo(H0.w), w[7]  - bf_hi(H0.w));
        L1.x = pack_bf16x2(w[8]  - bf_lo(H1.x), w[9]  - bf_hi(H1.x));
        L1.y = pack_bf16x2(w[10] - bf_lo(H1.y), w[11] - bf_hi(H1.y));
        L1.z = pack_bf16x2(w[12] - bf_lo(H1.z), w[13] - bf_hi(H1.z));
        L1.w = pack_bf16x2(w[14] - bf_lo(H1.w), w[15] - bf_hi(H1.w));
        const uint32_t o0 = sw128((uint32_t)(iw * 128 + kb * 2));
        const uint32_t o1 = sw128((uint32_t)(iw * 128 + kb * 2 + 16));
        *(uint4*)(smem + AHI[s] + o0) = H0;
        *(uint4*)(smem + AHI[s] + o1) = H1;
        *(uint4*)(smem + ALO[s] + o0) = L0;
        *(uint4*)(smem + ALO[s] + o1) = L1;
    };

    // ldmatrix lane address components
    const int aRow = lane & 15;            // A: row within 16-tile
    const int aH   = lane >> 4;            // A: k-half
    const int bRow = (lane & 7) | ((lane >> 4) << 3);  // B: n-row within 16
    const int bH   = (lane >> 3) & 1;      // B: k-half

    // ---- prologue: fill stage 0 ----
    load_B(0, 0);
    cp_commit();
    gen_A(0, 0);
    cp_wait0();
    __syncthreads();

    #pragma unroll 1
    for (int jt = 0; jt < NCHUNK; ++jt) {
        const int s = jt & 1;
        if (jt + 1 < NCHUNK) {
            load_B(jt + 1, s ^ 1);
            cp_commit();
            gen_A(jt + 1, s ^ 1);
        }

        // ---- MMA on stage s ----
        #pragma unroll
        for (int kk = 0; kk < 4; kk++) {
            uint32_t ah[2][4];
            #pragma unroll
            for (int mt = 0; mt < 2; mt++)
                ldsm4(ah[mt], sb + AHI[s] + sw128((uint32_t)(
                    (wm * 32 + mt * 16 + aRow) * 128 + kk * 32 + aH * 16)));
            uint32_t bh[4][4];
            #pragma unroll
            for (int p = 0; p < 4; p++)
                ldsm4(bh[p], sb + BHI[s] + sw128((uint32_t)(
                    (wn * 64 + p * 16 + bRow) * 128 + kk * 32 + bH * 16)));
            // product 1: Ah * Bh
            #pragma unroll
            for (int mt = 0; mt < 2; mt++)
                #pragma unroll
                for (int p = 0; p < 4; p++) {
                    mma16816(acc[mt][2 * p],     ah[mt], bh[p][0], bh[p][1]);
                    mma16816(acc[mt][2 * p + 1], ah[mt], bh[p][2], bh[p][3]);
                }
            // product 3: Al * Bh (bh still live)
            {
                uint32_t al[2][4];
                #pragma unroll
                for (int mt = 0; mt < 2; mt++)
                    ldsm4(al[mt], sb + ALO[s] + sw128((uint32_t)(
                        (wm * 32 + mt * 16 + aRow) * 128 + kk * 32 + aH * 16)));
                #pragma unroll
                for (int mt = 0; mt < 2; mt++)
                    #pragma unroll
                    for (int p = 0; p < 4; p++) {
                        mma16816(acc[mt][2 * p],     al[mt], bh[p][0], bh[p][1]);
                        mma16816(acc[mt][2 * p + 1], al[mt], bh[p][2], bh[p][3]);
                    }
            }
            // product 2: Ah * Bl
            {
                uint32_t bl[4][4];
                #pragma unroll
                for (int p = 0; p < 4; p++)
                    ldsm4(bl[p], sb + BLO[s] + sw128((uint32_t)(
                        (wn * 64 + p * 16 + bRow) * 128 + kk * 32 + bH * 16)));
                #pragma unroll
                for (int mt = 0; mt < 2; mt++)
                    #pragma unroll
                    for (int p = 0; p < 4; p++) {
                        mma16816(acc[mt][2 * p],     ah[mt], bl[p][0], bl[p][1]);
                        mma16816(acc[mt][2 * p + 1], ah[mt], bl[p][2], bl[p][3]);
                    }
            }
        }

        if (jt + 1 < NCHUNK) cp_wait0();
        __syncthreads();
    }

    // ---- epilogue: partial numerators + partial Z ----
    {
        float* npb = g_np + (size_t)ks * NN * DOUT;
        const int g  = lane >> 2;
        const int tg = lane & 3;
        #pragma unroll
        for (int mt = 0; mt < 2; mt++)
            #pragma unroll
            for (int nt = 0; nt < 8; nt++) {
                const int r0  = i0 + wm * 32 + mt * 16 + g;
                const int col = wn * 64 + nt * 8 + tg * 2;
                *(float2*)(npb + (size_t)r0 * DOUT + col) =
                    make_float2(acc[mt][nt][0], acc[mt][nt][1]);
                *(float2*)(npb + (size_t)(r0 + 8) * DOUT + col) =
                    make_float2(acc[mt][nt][2], acc[mt][nt][3]);
            }
    }
    float* zb = (float*)(smem + ZOFF);
    zb[tid] = zacc;
    __syncthreads();
    if (tid < 128)
        g_zp[ks * NN + i0 + tid] =
            zb[4 * tid] + zb[4 * tid + 1] + zb[4 * tid + 2] + zb[4 * tid + 3];
}

// ---------------------------------------------------------------------------
// Kernel D: combine partials, softmax-normalize, ELU
// ---------------------------------------------------------------------------
__global__ void k_combine(float* __restrict__ out)
{
    const int row = blockIdx.x;
    const int c = threadIdx.x * 4;
    const float inv = 1.f / (g_zp[row] + g_zp[NN + row]);
    float4 p0 = *(const float4*)&g_np[(size_t)row * DOUT + c];
    float4 p1 = *(const float4*)&g_np[(size_t)(NN + row) * DOUT + c];
    float v[4] = {(p0.x + p1.x) * inv, (p0.y + p1.y) * inv,
                  (p0.z + p1.z) * inv, (p0.w + p1.w) * inv};
    #pragma unroll
    for (int q = 0; q < 4; q++)
        v[q] = (v[q] > 0.f) ? v[q] : expm1f(v[q]);
    *(float4*)&out[(size_t)row * DOUT + c] = make_float4(v[0], v[1], v[2], v[3]);
}

// ---------------------------------------------------------------------------
extern "C" void kernel_launch(void* const* d_in, const int* in_sizes, int n_in,
                              void* d_out, int out_size)
{
    const float* h   = (const float*)d_in[0];   // [8192, 512]
    const int*   adj = (const int*)  d_in[1];   // [8192, 8192]
    const float* W   = (const float*)d_in[2];   // [512, 256]
    const float* a   = (const float*)d_in[3];   // [512, 1]
    float* out = (float*)d_out;                 // [8192, 256]

    cudaFuncSetAttribute(k_gat_mma, cudaFuncAttributeMaxDynamicSharedMemorySize,
                         SMEM_TOTAL);

    k_gemm_hw<<<dim3(DOUT / 64, NN / 64), 256>>>(h, W);
    k_f1f2<<<NN / 8, dim3(32, 8)>>>(a);
    k_gat_mma<<<dim3(NN / 128, KSLICES), 512, SMEM_TOTAL>>>(adj);
    k_combine<<<NN, 64>>>(out);
}

// round 4
// speedup vs baseline: 3.5324x; 1.6700x over previous
#include <cuda_runtime.h>
#include <cuda_bf16.h>
#include <cstdint>

#define NN   8192
#define DIN  512
#define DOUT 256
#define KSLICES 2
#define KSL  (NN / KSLICES)     // 4096 k per slice
#define KT   64                 // k per chunk
#define NCHUNK (KSL / KT)       // 64

// ---------------- scratch (__device__ globals: allocation-free rule) --------
__device__ float          g_hW  [(size_t)NN * DOUT];      // fp32 hW (for f1f2)
__device__ float          g_f1  [NN];
__device__ float          g_f2  [NN];
__device__ float          g_fmax;
__device__ unsigned short g_hWT [(size_t)DOUT * NN];      // hW^T fp16 [col][row]
__device__ float          g_np  [(size_t)KSLICES * NN * DOUT]; // partial numerators
__device__ float          g_zp  [KSLICES * NN];                // partial Z

// ---------------- helpers ---------------------------------------------------
__device__ __forceinline__ uint32_t smem_u32(const void* p) {
    uint32_t a;
    asm("{ .reg .u64 t; cvta.to.shared.u64 t, %1; cvt.u32.u64 %0, t; }"
        : "=r"(a) : "l"(p));
    return a;
}
__device__ __forceinline__ uint32_t sw128(uint32_t off) {
    return off ^ ((off >> 3) & 0x70);
}
// packs (lo, hi) -> low 16 = f16(lo), high 16 = f16(hi)
__device__ __forceinline__ unsigned pack_f16x2(float lo, float hi) {
    unsigned r;
    asm("cvt.rn.f16x2.f32 %0, %1, %2;" : "=r"(r) : "f"(hi), "f"(lo));
    return r;
}
__device__ __forceinline__ void cp16(uint32_t smem, const void* g) {
    asm volatile("cp.async.cg.shared.global [%0], [%1], 16;"
                 :: "r"(smem), "l"(g));
}
__device__ __forceinline__ void cp_commit() {
    asm volatile("cp.async.commit_group;");
}
__device__ __forceinline__ void cp_wait0() {
    asm volatile("cp.async.wait_group 0;" ::: "memory");
}
__device__ __forceinline__ void ldsm4(uint32_t* r, uint32_t addr) {
    asm volatile("ldmatrix.sync.aligned.m8n8.x4.shared.b16 {%0,%1,%2,%3}, [%4];"
                 : "=r"(r[0]), "=r"(r[1]), "=r"(r[2]), "=r"(r[3]) : "r"(addr));
}
__device__ __forceinline__ void mma16816(float* c, const uint32_t* a,
                                         uint32_t b0, uint32_t b1) {
    asm volatile(
        "mma.sync.aligned.m16n8k16.row.col.f32.f16.f16.f32 "
        "{%0,%1,%2,%3},{%4,%5,%6,%7},{%8,%9},{%0,%1,%2,%3};"
        : "+f"(c[0]), "+f"(c[1]), "+f"(c[2]), "+f"(c[3])
        : "r"(a[0]), "r"(a[1]), "r"(a[2]), "r"(a[3]), "r"(b0), "r"(b1));
}

// ---------------------------------------------------------------------------
// Kernel A: g_hW = h @ W  (fp32)  +  epilogue: g_hWT fp16 (transposed)
// ---------------------------------------------------------------------------
__global__ __launch_bounds__(256) void k_gemm_hw(
    const float* __restrict__ h, const float* __restrict__ W)
{
    __shared__ float As[32][64];
    __shared__ float Bs[32][64];

    const int tid = threadIdx.x;
    const int c0  = blockIdx.x * 64;
    const int i0  = blockIdx.y * 64;
    const int tx  = tid & 15;
    const int ty  = tid >> 4;
    const int li  = tid >> 2;
    const int lk  = (tid & 3) * 8;
    const int bk  = tid >> 4;
    const int bc  = (tid & 15) * 4;

    float acc[4][4] = {};

    for (int k0 = 0; k0 < DIN; k0 += 32) {
        float4 a0 = *(const float4*)&h[(i0 + li) * DIN + k0 + lk];
        float4 a1 = *(const float4*)&h[(i0 + li) * DIN + k0 + lk + 4];
        float4 b0 = *(const float4*)&W[(k0 + bk) * DOUT + c0 + bc];
        float4 b1 = *(const float4*)&W[(k0 + bk + 16) * DOUT + c0 + bc];

        __syncthreads();
        As[lk + 0][li] = a0.x; As[lk + 1][li] = a0.y;
        As[lk + 2][li] = a0.z; As[lk + 3][li] = a0.w;
        As[lk + 4][li] = a1.x; As[lk + 5][li] = a1.y;
        As[lk + 6][li] = a1.z; As[lk + 7][li] = a1.w;
        *(float4*)&Bs[bk][bc]      = b0;
        *(float4*)&Bs[bk + 16][bc] = b1;
        __syncthreads();

        #pragma unroll
        for (int k = 0; k < 32; k++) {
            float4 af = *(const float4*)&As[k][ty * 4];
            float4 bf = *(const float4*)&Bs[k][tx * 4];
            float ar[4] = {af.x, af.y, af.z, af.w};
            float br[4] = {bf.x, bf.y, bf.z, bf.w};
            #pragma unroll
            for (int r = 0; r < 4; r++)
                #pragma unroll
                for (int c = 0; c < 4; c++)
                    acc[r][c] = fmaf(ar[r], br[c], acc[r][c]);
        }
    }

    #pragma unroll
    for (int r = 0; r < 4; r++) {
        float4 v = make_float4(acc[r][0], acc[r][1], acc[r][2], acc[r][3]);
        *(float4*)&g_hW[(size_t)(i0 + ty * 4 + r) * DOUT + c0 + tx * 4] = v;
    }
    // transposed fp16
    #pragma unroll
    for (int cc = 0; cc < 4; cc++) {
        const int c = c0 + tx * 4 + cc;
        unsigned p01 = pack_f16x2(acc[0][cc], acc[1][cc]);
        unsigned p23 = pack_f16x2(acc[2][cc], acc[3][cc]);
        size_t base = (size_t)c * NN + i0 + ty * 4;
        *(uint2*)(g_hWT + base) = make_uint2(p01, p23);
    }
}

// ---------------------------------------------------------------------------
// Kernel B: f1 = hW @ a[:256],  f2 = hW @ a[256:]
// ---------------------------------------------------------------------------
__global__ void k_f1f2(const float* __restrict__ a)
{
    const int row  = blockIdx.x * 8 + threadIdx.y;
    const int lane = threadIdx.x;
    const float* hw = &g_hW[(size_t)row * DOUT];

    float s1 = 0.f, s2 = 0.f;
    #pragma unroll
    for (int c = 0; c < DOUT; c += 32) {
        float v = hw[c + lane];
        s1 = fmaf(v, a[c + lane], s1);
        s2 = fmaf(v, a[DOUT + c + lane], s2);
    }
    #pragma unroll
    for (int off = 16; off; off >>= 1) {
        s1 += __shfl_xor_sync(0xffffffffu, s1, off);
        s2 += __shfl_xor_sync(0xffffffffu, s2, off);
    }
    if (lane == 0) { g_f1[row] = s1; g_f2[row] = s2; }
}

// ---------------------------------------------------------------------------
// Kernel B2: g_fmax = max(f2)
// ---------------------------------------------------------------------------
__global__ void k_fmax()
{
    __shared__ float sred[32];
    const int tid = threadIdx.x;   // 1024 threads
    float m = -1e30f;
    #pragma unroll
    for (int i = tid; i < NN; i += 1024) m = fmaxf(m, g_f2[i]);
    #pragma unroll
    for (int o = 16; o; o >>= 1) m = fmaxf(m, __shfl_xor_sync(~0u, m, o));
    if ((tid & 31) == 0) sred[tid >> 5] = m;
    __syncthreads();
    if (tid < 32) {
        float v = sred[tid];
        #pragma unroll
        for (int o = 16; o; o >>= 1) v = fmaxf(v, __shfl_xor_sync(~0u, v, o));
        if (tid == 0) g_fmax = v;
    }
}

// ---------------------------------------------------------------------------
// Kernel C: warp-MMA (mma.sync fp16, SINGLE product) masked-softmax agg.
// Max-subtraction: w' = exp(leaky(f1_i+f2_j) - M_i), M_i = leaky(f1_i+Fmax)
// => w' in (0,1], fp16-safe. Scale cancels in numerator/Z ratio.
// Grid (64, KSLICES), 512 threads (16 warps, 4m x 4n).
// ---------------------------------------------------------------------------
// SMEM: [0..2KB) zbuf; stages at 2KB: per stage A 16K | B 32K
#define ZOFF        0
#define TILE0       2048
#define STAGE_BYTES 49152
#define SMEM_TOTAL  (TILE0 + 2 * STAGE_BYTES)

__global__ __launch_bounds__(512, 1) void k_gat_mma(const int* __restrict__ adj)
{
    extern __shared__ __align__(1024) char smem[];
    const uint32_t sb = smem_u32(smem);

    const int tid  = threadIdx.x;
    const int lane = tid & 31;
    const int wid  = tid >> 5;
    const int wm   = wid & 3;      // warp row  (32 rows)
    const int wn   = wid >> 2;     // warp col  (64 cols)
    const int i0   = blockIdx.x * 128;
    const int ks   = blockIdx.y;
    const int k0s  = ks * KSL;

    int AHI[2], BHI[2];
    #pragma unroll
    for (int s = 0; s < 2; s++) {
        AHI[s] = TILE0 + s * STAGE_BYTES;
        BHI[s] = AHI[s] + 16384;
    }

    // ---- w-gen mapping: row iw, 16 k's starting at kb ----
    const int iw = tid >> 2;
    const int kb = (tid & 3) * 16;
    const float f1v  = g_f1[i0 + iw];
    const float smax = f1v + g_fmax;
    const float Mrow = fmaxf(smax, 0.2f * smax);   // leaky(f1+Fmax) >= all e
    float zacc = 0.f;

    // ---- B cp.async mapping: n-row rB, 4 chunks of 16B ----
    const int rB   = tid & 255;
    const int half = tid >> 8;

    float acc[2][8][4];
    #pragma unroll
    for (int mt = 0; mt < 2; mt++)
        #pragma unroll
        for (int nt = 0; nt < 8; nt++)
            #pragma unroll
            for (int q = 0; q < 4; q++) acc[mt][nt][q] = 0.f;

    auto load_B = [&](int jt, int s) {
        const size_t gk = (size_t)rB * NN + k0s + jt * KT;
        #pragma unroll
        for (int c = 0; c < 4; c++) {
            const int cc = half * 4 + c;
            const uint32_t off = sw128((uint32_t)(rB * 128 + cc * 16));
            cp16(sb + BHI[s] + off, g_hWT + gk + cc * 8);
        }
    };

    auto gen_A = [&](int jt, int s) {
        const size_t kg = (size_t)k0s + jt * KT + kb;
        const int4*   ap = (const int4*)  (adj  + (size_t)(i0 + iw) * NN + kg);
        const float4* fp = (const float4*)(g_f2 + kg);
        int4   A0 = ap[0], A1 = ap[1], A2 = ap[2], A3 = ap[3];
        float4 F0 = fp[0], F1 = fp[1], F2 = fp[2], F3 = fp[3];
        const int   av[16] = {A0.x,A0.y,A0.z,A0.w, A1.x,A1.y,A1.z,A1.w,
                              A2.x,A2.y,A2.z,A2.w, A3.x,A3.y,A3.z,A3.w};
        const float fv[16] = {F0.x,F0.y,F0.z,F0.w, F1.x,F1.y,F1.z,F1.w,
                              F2.x,F2.y,F2.z,F2.w, F3.x,F3.y,F3.z,F3.w};
        float w[16];
        #pragma unroll
        for (int q = 0; q < 16; q++) {
            float sv = f1v + fv[q];
            float e  = fmaxf(sv, 0.2f * sv);     // leaky
            float we = __expf(e - Mrow);         // in (0,1]
            w[q] = (av[q] > 0) ? we : 0.f;
            zacc += w[q];
        }
        uint4 H0, H1;
        H0.x = pack_f16x2(w[0],  w[1]);  H0.y = pack_f16x2(w[2],  w[3]);
        H0.z = pack_f16x2(w[4],  w[5]);  H0.w = pack_f16x2(w[6],  w[7]);
        H1.x = pack_f16x2(w[8],  w[9]);  H1.y = pack_f16x2(w[10], w[11]);
        H1.z = pack_f16x2(w[12], w[13]); H1.w = pack_f16x2(w[14], w[15]);
        const uint32_t o0 = sw128((uint32_t)(iw * 128 + kb * 2));
        const uint32_t o1 = sw128((uint32_t)(iw * 128 + kb * 2 + 16));
        *(uint4*)(smem + AHI[s] + o0) = H0;
        *(uint4*)(smem + AHI[s] + o1) = H1;
    };

    // ldmatrix lane address components
    const int aRow = lane & 15;                        // A: row within 16-tile
    const int aH   = lane >> 4;                        // A: k-half
    const int bRow = (lane & 7) | ((lane >> 4) << 3);  // B: n-row within 16
    const int bH   = (lane >> 3) & 1;                  // B: k-half

    // ---- prologue: fill stage 0 ----
    load_B(0, 0);
    cp_commit();
    gen_A(0, 0);
    cp_wait0();
    __syncthreads();

    #pragma unroll 1
    for (int jt = 0; jt < NCHUNK; ++jt) {
        const int s = jt & 1;
        if (jt + 1 < NCHUNK) {
            load_B(jt + 1, s ^ 1);
            cp_commit();
            gen_A(jt + 1, s ^ 1);
        }

        // ---- MMA on stage s: single product A*B ----
        #pragma unroll
        for (int kk = 0; kk < 4; kk++) {
            uint32_t ah[2][4];
            #pragma unroll
            for (int mt = 0; mt < 2; mt++)
                ldsm4(ah[mt], sb + AHI[s] + sw128((uint32_t)(
                    (wm * 32 + mt * 16 + aRow) * 128 + kk * 32 + aH * 16)));
            uint32_t bh[4][4];
            #pragma unroll
            for (int p = 0; p < 4; p++)
                ldsm4(bh[p], sb + BHI[s] + sw128((uint32_t)(
                    (wn * 64 + p * 16 + bRow) * 128 + kk * 32 + bH * 16)));
            #pragma unroll
            for (int mt = 0; mt < 2; mt++)
                #pragma unroll
                for (int p = 0; p < 4; p++) {
                    mma16816(acc[mt][2 * p],     ah[mt], bh[p][0], bh[p][1]);
                    mma16816(acc[mt][2 * p + 1], ah[mt], bh[p][2], bh[p][3]);
                }
        }

        if (jt + 1 < NCHUNK) cp_wait0();
        __syncthreads();
    }

    // ---- epilogue: partial numerators + partial Z ----
    {
        float* npb = g_np + (size_t)ks * NN * DOUT;
        const int g  = lane >> 2;
        const int tg = lane & 3;
        #pragma unroll
        for (int mt = 0; mt < 2; mt++)
            #pragma unroll
            for (int nt = 0; nt < 8; nt++) {
                const int r0  = i0 + wm * 32 + mt * 16 + g;
                const int col = wn * 64 + nt * 8 + tg * 2;
                *(float2*)(npb + (size_t)r0 * DOUT + col) =
                    make_float2(acc[mt][nt][0], acc[mt][nt][1]);
                *(float2*)(npb + (size_t)(r0 + 8) * DOUT + col) =
                    make_float2(acc[mt][nt][2], acc[mt][nt][3]);
            }
    }
    float* zb = (float*)(smem + ZOFF);
    zb[tid] = zacc;
    __syncthreads();
    if (tid < 128)
        g_zp[ks * NN + i0 + tid] =
            zb[4 * tid] + zb[4 * tid + 1] + zb[4 * tid + 2] + zb[4 * tid + 3];
}

// ---------------------------------------------------------------------------
// Kernel D: combine partials, softmax-normalize, ELU
// ---------------------------------------------------------------------------
__global__ void k_combine(float* __restrict__ out)
{
    const int row = blockIdx.x;
    const int c = threadIdx.x * 4;
    const float inv = 1.f / (g_zp[row] + g_zp[NN + row]);
    float4 p0 = *(const float4*)&g_np[(size_t)row * DOUT + c];
    float4 p1 = *(const float4*)&g_np[(size_t)(NN + row) * DOUT + c];
    float v[4] = {(p0.x + p1.x) * inv, (p0.y + p1.y) * inv,
                  (p0.z + p1.z) * inv, (p0.w + p1.w) * inv};
    #pragma unroll
    for (int q = 0; q < 4; q++)
        v[q] = (v[q] > 0.f) ? v[q] : expm1f(v[q]);
    *(float4*)&out[(size_t)row * DOUT + c] = make_float4(v[0], v[1], v[2], v[3]);
}

// ---------------------------------------------------------------------------
extern "C" void kernel_launch(void* const* d_in, const int* in_sizes, int n_in,
                              void* d_out, int out_size)
{
    const float* h   = (const float*)d_in[0];   // [8192, 512]
    const int*   adj = (const int*)  d_in[1];   // [8192, 8192]
    const float* W   = (const float*)d_in[2];   // [512, 256]
    const float* a   = (const float*)d_in[3];   // [512, 1]
    float* out = (float*)d_out;                 // [8192, 256]

    cudaFuncSetAttribute(k_gat_mma, cudaFuncAttributeMaxDynamicSharedMemorySize,
                         SMEM_TOTAL);

    k_gemm_hw<<<dim3(DOUT / 64, NN / 64), 256>>>(h, W);
    k_f1f2<<<NN / 8, dim3(32, 8)>>>(a);
    k_fmax<<<1, 1024>>>();
    k_gat_mma<<<dim3(NN / 128, KSLICES), 512, SMEM_TOTAL>>>(adj);
    k_combine<<<NN, 64>>>(out);
}

// round 5
// speedup vs baseline: 3.6190x; 1.0245x over previous
#include <cuda_runtime.h>
#include <cuda_bf16.h>
#include <cstdint>

#define NN   8192
#define DIN  512
#define DOUT 256
#define KSLICES 2
#define KSL  (NN / KSLICES)     // 4096 k per slice
#define KT   64                 // k per chunk
#define NCHUNK (KSL / KT)       // 64

// ---------------- scratch (__device__ globals: allocation-free rule) --------
__device__ float          g_hW  [(size_t)NN * DOUT];      // fp32 hW (for f1f2)
__device__ float          g_f1  [NN];
__device__ float          g_f2  [NN];
__device__ float          g_fmax;
__device__ unsigned short g_hWT [(size_t)DOUT * NN];      // hW^T fp16 [col][row]
__device__ float          g_np  [(size_t)KSLICES * NN * DOUT]; // partial numerators
__device__ float          g_zp  [KSLICES * NN];                // partial Z

// ---------------- helpers ---------------------------------------------------
__device__ __forceinline__ uint32_t smem_u32(const void* p) {
    uint32_t a;
    asm("{ .reg .u64 t; cvta.to.shared.u64 t, %1; cvt.u32.u64 %0, t; }"
        : "=r"(a) : "l"(p));
    return a;
}
__device__ __forceinline__ uint32_t sw128(uint32_t off) {
    return off ^ ((off >> 3) & 0x70);
}
// packs (lo, hi) -> low 16 = f16(lo), high 16 = f16(hi)
__device__ __forceinline__ unsigned pack_f16x2(float lo, float hi) {
    unsigned r;
    asm("cvt.rn.f16x2.f32 %0, %1, %2;" : "=r"(r) : "f"(hi), "f"(lo));
    return r;
}
__device__ __forceinline__ void cp16(uint32_t smem, const void* g) {
    asm volatile("cp.async.cg.shared.global [%0], [%1], 16;"
                 :: "r"(smem), "l"(g));
}
__device__ __forceinline__ void cp_commit() {
    asm volatile("cp.async.commit_group;");
}
__device__ __forceinline__ void cp_wait0() {
    asm volatile("cp.async.wait_group 0;" ::: "memory");
}
__device__ __forceinline__ void ldsm4(uint32_t* r, uint32_t addr) {
    asm volatile("ldmatrix.sync.aligned.m8n8.x4.shared.b16 {%0,%1,%2,%3}, [%4];"
                 : "=r"(r[0]), "=r"(r[1]), "=r"(r[2]), "=r"(r[3]) : "r"(addr));
}
__device__ __forceinline__ void mma16816(float* c, const uint32_t* a,
                                         uint32_t b0, uint32_t b1) {
    asm volatile(
        "mma.sync.aligned.m16n8k16.row.col.f32.f16.f16.f32 "
        "{%0,%1,%2,%3},{%4,%5,%6,%7},{%8,%9},{%0,%1,%2,%3};"
        : "+f"(c[0]), "+f"(c[1]), "+f"(c[2]), "+f"(c[3])
        : "r"(a[0]), "r"(a[1]), "r"(a[2]), "r"(a[3]), "r"(b0), "r"(b1));
}

// ---------------------------------------------------------------------------
// Kernel A: g_hW = h @ W  (fp32)  +  epilogue: g_hWT fp16 (transposed)
// 128x64 tile, 256 threads, 8x4 micro-tile.
// ---------------------------------------------------------------------------
__global__ __launch_bounds__(256) void k_gemm_hw(
    const float* __restrict__ h, const float* __restrict__ W)
{
    __shared__ float As[32][128];  // [k][m] 16 KB
    __shared__ float Bs[32][64];   // [k][n]  8 KB

    const int tid = threadIdx.x;
    const int c0  = blockIdx.x * 64;
    const int i0  = blockIdx.y * 128;
    const int tx  = tid & 15;            // 4 cols
    const int ty  = tid >> 4;            // 8 rows

    const int li  = tid >> 1;            // 0..127 A-load row
    const int lk  = (tid & 1) * 16;      // A-load k base (16 k's)

    const int bk  = tid >> 3;            // 0..31  B-load k
    const int bc  = (tid & 7) * 8;       // B-load col (8 cols)

    float acc[8][4] = {};

    for (int k0 = 0; k0 < DIN; k0 += 32) {
        float4 a0 = *(const float4*)&h[(i0 + li) * DIN + k0 + lk];
        float4 a1 = *(const float4*)&h[(i0 + li) * DIN + k0 + lk + 4];
        float4 a2 = *(const float4*)&h[(i0 + li) * DIN + k0 + lk + 8];
        float4 a3 = *(const float4*)&h[(i0 + li) * DIN + k0 + lk + 12];
        float4 b0 = *(const float4*)&W[(k0 + bk) * DOUT + c0 + bc];
        float4 b1 = *(const float4*)&W[(k0 + bk) * DOUT + c0 + bc + 4];

        __syncthreads();
        As[lk +  0][li] = a0.x; As[lk +  1][li] = a0.y;
        As[lk +  2][li] = a0.z; As[lk +  3][li] = a0.w;
        As[lk +  4][li] = a1.x; As[lk +  5][li] = a1.y;
        As[lk +  6][li] = a1.z; As[lk +  7][li] = a1.w;
        As[lk +  8][li] = a2.x; As[lk +  9][li] = a2.y;
        As[lk + 10][li] = a2.z; As[lk + 11][li] = a2.w;
        As[lk + 12][li] = a3.x; As[lk + 13][li] = a3.y;
        As[lk + 14][li] = a3.z; As[lk + 15][li] = a3.w;
        *(float4*)&Bs[bk][bc]     = b0;
        *(float4*)&Bs[bk][bc + 4] = b1;
        __syncthreads();

        #pragma unroll
        for (int k = 0; k < 32; k++) {
            float4 af0 = *(const float4*)&As[k][ty * 8];
            float4 af1 = *(const float4*)&As[k][ty * 8 + 4];
            float4 bf  = *(const float4*)&Bs[k][tx * 4];
            float ar[8] = {af0.x, af0.y, af0.z, af0.w,
                           af1.x, af1.y, af1.z, af1.w};
            float br[4] = {bf.x, bf.y, bf.z, bf.w};
            #pragma unroll
            for (int r = 0; r < 8; r++)
                #pragma unroll
                for (int c = 0; c < 4; c++)
                    acc[r][c] = fmaf(ar[r], br[c], acc[r][c]);
        }
    }

    #pragma unroll
    for (int r = 0; r < 8; r++) {
        float4 v = make_float4(acc[r][0], acc[r][1], acc[r][2], acc[r][3]);
        *(float4*)&g_hW[(size_t)(i0 + ty * 8 + r) * DOUT + c0 + tx * 4] = v;
    }
    // transposed fp16: 8 rows per column -> one uint4
    #pragma unroll
    for (int cc = 0; cc < 4; cc++) {
        const int c = c0 + tx * 4 + cc;
        uint4 p;
        p.x = pack_f16x2(acc[0][cc], acc[1][cc]);
        p.y = pack_f16x2(acc[2][cc], acc[3][cc]);
        p.z = pack_f16x2(acc[4][cc], acc[5][cc]);
        p.w = pack_f16x2(acc[6][cc], acc[7][cc]);
        *(uint4*)(g_hWT + (size_t)c * NN + i0 + ty * 8) = p;
    }
}

// ---------------------------------------------------------------------------
// Kernel B: f1 = hW @ a[:256],  f2 = hW @ a[256:]
// ---------------------------------------------------------------------------
__global__ void k_f1f2(const float* __restrict__ a)
{
    const int row  = blockIdx.x * 8 + threadIdx.y;
    const int lane = threadIdx.x;
    const float* hw = &g_hW[(size_t)row * DOUT];

    float s1 = 0.f, s2 = 0.f;
    #pragma unroll
    for (int c = 0; c < DOUT; c += 32) {
        float v = hw[c + lane];
        s1 = fmaf(v, a[c + lane], s1);
        s2 = fmaf(v, a[DOUT + c + lane], s2);
    }
    #pragma unroll
    for (int off = 16; off; off >>= 1) {
        s1 += __shfl_xor_sync(0xffffffffu, s1, off);
        s2 += __shfl_xor_sync(0xffffffffu, s2, off);
    }
    if (lane == 0) { g_f1[row] = s1; g_f2[row] = s2; }
}

// ---------------------------------------------------------------------------
// Kernel B2: g_fmax = max(f2)
// ---------------------------------------------------------------------------
__global__ void k_fmax()
{
    __shared__ float sred[32];
    const int tid = threadIdx.x;   // 1024 threads
    float m = -1e30f;
    #pragma unroll
    for (int i = tid; i < NN; i += 1024) m = fmaxf(m, g_f2[i]);
    #pragma unroll
    for (int o = 16; o; o >>= 1) m = fmaxf(m, __shfl_xor_sync(~0u, m, o));
    if ((tid & 31) == 0) sred[tid >> 5] = m;
    __syncthreads();
    if (tid < 32) {
        float v = sred[tid];
        #pragma unroll
        for (int o = 16; o; o >>= 1) v = fmaxf(v, __shfl_xor_sync(~0u, v, o));
        if (tid == 0) g_fmax = v;
    }
}

// ---------------------------------------------------------------------------
// Kernel C: warp-MMA (mma.sync fp16) masked-softmax aggregation.
// M=64 x N=256 CTA tile, 256 threads (8 warps, 2m x 4n), 2 CTAs/SM.
// Max-subtraction keeps w in (0,1] => single fp16 product.
// Grid (128, KSLICES).
// ---------------------------------------------------------------------------
// SMEM: [0..1KB) zbuf; stages at 2KB: per stage A 8K | B 32K
#define ZOFF        0
#define TILE0       2048
#define STAGE_BYTES 40960
#define SMEM_TOTAL  (TILE0 + 2 * STAGE_BYTES)

__global__ __launch_bounds__(256, 2) void k_gat_mma(const int* __restrict__ adj)
{
    extern __shared__ __align__(1024) char smem[];
    const uint32_t sb = smem_u32(smem);

    const int tid  = threadIdx.x;
    const int lane = tid & 31;
    const int wid  = tid >> 5;
    const int wm   = wid & 1;      // warp row  (32 rows)
    const int wn   = wid >> 1;     // warp col  (64 cols)
    const int i0   = blockIdx.x * 64;
    const int ks   = blockIdx.y;
    const int k0s  = ks * KSL;

    int AHI[2], BHI[2];
    #pragma unroll
    for (int s = 0; s < 2; s++) {
        AHI[s] = TILE0 + s * STAGE_BYTES;
        BHI[s] = AHI[s] + 8192;
    }

    // ---- w-gen mapping: row iw, 16 k's starting at kb ----
    const int iw = tid >> 2;             // 0..63
    const int kb = (tid & 3) * 16;
    const float f1v  = g_f1[i0 + iw];
    const float smax = f1v + g_fmax;
    const float Mrow = fmaxf(smax, 0.2f * smax);   // leaky(f1+Fmax) >= all e
    float zacc = 0.f;

    // ---- B cp.async mapping: n-row = tid, 8 chunks of 16B ----
    const int rB = tid;

    float acc[2][8][4];
    #pragma unroll
    for (int mt = 0; mt < 2; mt++)
        #pragma unroll
        for (int nt = 0; nt < 8; nt++)
            #pragma unroll
            for (int q = 0; q < 4; q++) acc[mt][nt][q] = 0.f;

    auto load_B = [&](int jt, int s) {
        const size_t gk = (size_t)rB * NN + k0s + jt * KT;
        #pragma unroll
        for (int cc = 0; cc < 8; cc++) {
            const uint32_t off = sw128((uint32_t)(rB * 128 + cc * 16));
            cp16(sb + BHI[s] + off, g_hWT + gk + cc * 8);
        }
    };

    auto gen_A = [&](int jt, int s) {
        const size_t kg = (size_t)k0s + jt * KT + kb;
        const int4*   ap = (const int4*)  (adj  + (size_t)(i0 + iw) * NN + kg);
        const float4* fp = (const float4*)(g_f2 + kg);
        int4   A0 = ap[0], A1 = ap[1], A2 = ap[2], A3 = ap[3];
        float4 F0 = fp[0], F1 = fp[1], F2 = fp[2], F3 = fp[3];
        const int   av[16] = {A0.x,A0.y,A0.z,A0.w, A1.x,A1.y,A1.z,A1.w,
                              A2.x,A2.y,A2.z,A2.w, A3.x,A3.y,A3.z,A3.w};
        const float fv[16] = {F0.x,F0.y,F0.z,F0.w, F1.x,F1.y,F1.z,F1.w,
                              F2.x,F2.y,F2.z,F2.w, F3.x,F3.y,F3.z,F3.w};
        float w[16];
        #pragma unroll
        for (int q = 0; q < 16; q++) {
            float sv = f1v + fv[q];
            float e  = fmaxf(sv, 0.2f * sv);     // leaky
            float we = __expf(e - Mrow);         // in (0,1]
            w[q] = (av[q] > 0) ? we : 0.f;
            zacc += w[q];
        }
        uint4 H0, H1;
        H0.x = pack_f16x2(w[0],  w[1]);  H0.y = pack_f16x2(w[2],  w[3]);
        H0.z = pack_f16x2(w[4],  w[5]);  H0.w = pack_f16x2(w[6],  w[7]);
        H1.x = pack_f16x2(w[8],  w[9]);  H1.y = pack_f16x2(w[10], w[11]);
        H1.z = pack_f16x2(w[12], w[13]); H1.w = pack_f16x2(w[14], w[15]);
        const uint32_t o0 = sw128((uint32_t)(iw * 128 + kb * 2));
        const uint32_t o1 = sw128((uint32_t)(iw * 128 + kb * 2 + 16));
        *(uint4*)(smem + AHI[s] + o0) = H0;
        *(uint4*)(smem + AHI[s] + o1) = H1;
    };

    // ldmatrix lane address components
    const int aRow = lane & 15;                        // A: row within 16-tile
    const int aH   = lane >> 4;                        // A: k-half
    const int bRow = (lane & 7) | ((lane >> 4) << 3);  // B: n-row within 16
    const int bH   = (lane >> 3) & 1;                  // B: k-half

    // ---- prologue: fill stage 0 ----
    load_B(0, 0);
    cp_commit();
    gen_A(0, 0);
    cp_wait0();
    __syncthreads();

    #pragma unroll 1
    for (int jt = 0; jt < NCHUNK; ++jt) {
        const int s = jt & 1;
        if (jt + 1 < NCHUNK) {
            load_B(jt + 1, s ^ 1);
            cp_commit();
            gen_A(jt + 1, s ^ 1);
        }

        // ---- MMA on stage s ----
        #pragma unroll
        for (int kk = 0; kk < 4; kk++) {
            uint32_t ah[2][4];
            #pragma unroll
            for (int mt = 0; mt < 2; mt++)
                ldsm4(ah[mt], sb + AHI[s] + sw128((uint32_t)(
                    (wm * 32 + mt * 16 + aRow) * 128 + kk * 32 + aH * 16)));
            uint32_t bh[4][4];
            #pragma unroll
            for (int p = 0; p < 4; p++)
                ldsm4(bh[p], sb + BHI[s] + sw128((uint32_t)(
                    (wn * 64 + p * 16 + bRow) * 128 + kk * 32 + bH * 16)));
            #pragma unroll
            for (int mt = 0; mt < 2; mt++)
                #pragma unroll
                for (int p = 0; p < 4; p++) {
                    mma16816(acc[mt][2 * p],     ah[mt], bh[p][0], bh[p][1]);
                    mma16816(acc[mt][2 * p + 1], ah[mt], bh[p][2], bh[p][3]);
                }
        }

        if (jt + 1 < NCHUNK) cp_wait0();
        __syncthreads();
    }

    // ---- epilogue: partial numerators + partial Z ----
    {
        float* npb = g_np + (size_t)ks * NN * DOUT;
        const int g  = lane >> 2;
        const int tg = lane & 3;
        #pragma unroll
        for (int mt = 0; mt < 2; mt++)
            #pragma unroll
            for (int nt = 0; nt < 8; nt++) {
                const int r0  = i0 + wm * 32 + mt * 16 + g;
                const int col = wn * 64 + nt * 8 + tg * 2;
                *(float2*)(npb + (size_t)r0 * DOUT + col) =
                    make_float2(acc[mt][nt][0], acc[mt][nt][1]);
                *(float2*)(npb + (size_t)(r0 + 8) * DOUT + col) =
                    make_float2(acc[mt][nt][2], acc[mt][nt][3]);
            }
    }
    float* zb = (float*)(smem + ZOFF);
    zb[tid] = zacc;
    __syncthreads();
    if (tid < 64)
        g_zp[ks * NN + i0 + tid] =
            zb[4 * tid] + zb[4 * tid + 1] + zb[4 * tid + 2] + zb[4 * tid + 3];
}

// ---------------------------------------------------------------------------
// Kernel D: combine partials, softmax-normalize, ELU
// ---------------------------------------------------------------------------
__global__ void k_combine(float* __restrict__ out)
{
    const int row = blockIdx.x;
    const int c = threadIdx.x * 4;
    const float inv = 1.f / (g_zp[row] + g_zp[NN + row]);
    float4 p0 = *(const float4*)&g_np[(size_t)row * DOUT + c];
    float4 p1 = *(const float4*)&g_np[(size_t)(NN + row) * DOUT + c];
    float v[4] = {(p0.x + p1.x) * inv, (p0.y + p1.y) * inv,
                  (p0.z + p1.z) * inv, (p0.w + p1.w) * inv};
    #pragma unroll
    for (int q = 0; q < 4; q++)
        v[q] = (v[q] > 0.f) ? v[q] : expm1f(v[q]);
    *(float4*)&out[(size_t)row * DOUT + c] = make_float4(v[0], v[1], v[2], v[3]);
}

// ---------------------------------------------------------------------------
extern "C" void kernel_launch(void* const* d_in, const int* in_sizes, int n_in,
                              void* d_out, int out_size)
{
    const float* h   = (const float*)d_in[0];   // [8192, 512]
    const int*   adj = (const int*)  d_in[1];   // [8192, 8192]
    const float* W   = (const float*)d_in[2];   // [512, 256]
    const float* a   = (const float*)d_in[3];   // [512, 1]
    float* out = (float*)d_out;                 // [8192, 256]

    cudaFuncSetAttribute(k_gat_mma, cudaFuncAttributeMaxDynamicSharedMemorySize,
                         SMEM_TOTAL);

    k_gemm_hw<<<dim3(DOUT / 64, NN / 128), 256>>>(h, W);
    k_f1f2<<<NN / 8, dim3(32, 8)>>>(a);
    k_fmax<<<1, 1024>>>();
    k_gat_mma<<<dim3(NN / 64, KSLICES), 256, SMEM_TOTAL>>>(adj);
    k_combine<<<NN, 64>>>(out);
}